// round 2
// baseline (speedup 1.0000x reference)
#include <cuda_runtime.h>

// StereoDenoiser: B=8, C=3, H=1024, W=1920, fp32.
//   disp  = clip(depth*128, 0, 128)            [B,H,W]
//   warped_r = bilinear_x(img_r, x = w - disp) (border clamp)
//   warped_l = bilinear_x(img_l, x = w + disp)
//   out_l = (img_l + warped_r)*0.5 ; out_r = (img_r + warped_l)*0.5
// Output buffer: [out_l | out_r], each B*C*H*W floats.

#define BATCH 8
#define CH 3
#define HH 1024
#define WW 1920
#define MAXD 128.0f

__global__ __launch_bounds__(256, 6) void stereo_denoise_kernel(
    const float* __restrict__ img_l,
    const float* __restrict__ img_r,
    const float* __restrict__ depth,
    float* __restrict__ out)
{
    const int UNITS = WW / 4;                 // 480 float4 units per row
    const int total = BATCH * HH * UNITS;     // 3,932,160
    int tid = blockIdx.x * blockDim.x + threadIdx.x;
    if (tid >= total) return;

    int u   = tid % UNITS;
    int row = tid / UNITS;                    // b*HH + h
    int b   = row / HH;
    int h   = row - b * HH;
    int w0  = u * 4;

    // depth is [B,1,H,W] -> row-linear; read-once -> streaming load
    const float4* dep4 = reinterpret_cast<const float4*>(depth + (size_t)row * WW + w0);
    float4 dep = __ldcs(dep4);
    float d[4] = {dep.x, dep.y, dep.z, dep.w};

    int   i0L[4], i0R[4];
    float fL[4], fR[4];
#pragma unroll
    for (int p = 0; p < 4; ++p) {
        float disp = fminf(fmaxf(d[p] * MAXD, 0.0f), MAXD);
        float xw = (float)(w0 + p);

        // warped_r samples img_r at x = w - disp  (sign = -1)
        float xl = fminf(fmaxf(xw - disp, 0.0f), (float)(WW - 1));
        int i0 = (int)xl;                 // xl >= 0 -> trunc == floor
        fL[p]  = xl - (float)i0;
        i0L[p] = i0;

        // warped_l samples img_l at x = w + disp  (sign = +1)
        float xr = fminf(fmaxf(xw + disp, 0.0f), (float)(WW - 1));
        int j0 = (int)xr;
        fR[p]  = xr - (float)j0;
        i0R[p] = j0;
    }

    const int HW = HH * WW;
    const int N  = BATCH * CH * HW;           // 47,185,920 (fits int32)
    int plane0 = (b * CH) * HW + h * WW;      // c=0 row base for (b,h)

#pragma unroll
    for (int c = 0; c < CH; ++c) {
        int base = plane0 + c * HW;
        const float* rl = img_l + base;       // row base of img_l, channel c
        const float* rr = img_r + base;       // row base of img_r, channel c

        float4 lv = *reinterpret_cast<const float4*>(rl + w0);
        float4 rv = *reinterpret_cast<const float4*>(rr + w0);
        float lvv[4] = {lv.x, lv.y, lv.z, lv.w};
        float rvv[4] = {rv.x, rv.y, rv.z, rv.w};

        float ol[4], og[4];
#pragma unroll
        for (int p = 0; p < 4; ++p) {
            int a0 = i0L[p];
            int a1 = min(a0 + 1, WW - 1);
            int b0 = i0R[p];
            int b1 = min(b0 + 1, WW - 1);
            float wr = __ldg(rr + a0) * (1.0f - fL[p]) + __ldg(rr + a1) * fL[p];
            float wl = __ldg(rl + b0) * (1.0f - fR[p]) + __ldg(rl + b1) * fR[p];
            ol[p] = (lvv[p] + wr) * 0.5f;
            og[p] = (rvv[p] + wl) * 0.5f;
        }

        // outputs are never re-read: evict-first stores to keep L2 for gathers
        __stcs(reinterpret_cast<float4*>(out + base + w0),
               make_float4(ol[0], ol[1], ol[2], ol[3]));
        __stcs(reinterpret_cast<float4*>(out + N + base + w0),
               make_float4(og[0], og[1], og[2], og[3]));
    }
}

extern "C" void kernel_launch(void* const* d_in, const int* in_sizes, int n_in,
                              void* d_out, int out_size) {
    const float* img_l = (const float*)d_in[0];
    const float* img_r = (const float*)d_in[1];
    const float* depth = (const float*)d_in[2];
    float* out = (float*)d_out;

    const int total = BATCH * HH * (WW / 4);
    const int threads = 256;
    const int blocks = (total + threads - 1) / threads;
    stereo_denoise_kernel<<<blocks, threads>>>(img_l, img_r, depth, out);
}

// round 4
// speedup vs baseline: 1.4486x; 1.4486x over previous
#include <cuda_runtime.h>

// StereoDenoiser: B=8, C=3, H=1024, W=1920, fp32.
//   disp  = clip(depth*128, 0, 128)            [B,H,W]
//   warped_r = bilinear_x(img_r, x = w - disp) (border clamp)
//   warped_l = bilinear_x(img_l, x = w + disp)
//   out_l = (img_l + warped_r)*0.5 ; out_r = (img_r + warped_l)*0.5
// Output buffer: [out_l | out_r], each B*C*H*W floats.
//
// Strategy: one block per (b,h) image row. Stage both image rows in shared
// memory (the same float4 loads also feed the pass-through term), serve all
// bilinear gather taps from LDS. L1tex sees only coalesced float4 traffic.

#define BATCH 8
#define CH 3
#define HH 1024
#define WW 1920
#define MAXD 128.0f

__global__ __launch_bounds__(480) void stereo_denoise_kernel(
    const float* __restrict__ img_l,
    const float* __restrict__ img_r,
    const float* __restrict__ depth,
    float* __restrict__ out)
{
    __shared__ float sl[WW];
    __shared__ float sr[WW];

    const int row = blockIdx.x;          // b*HH + h
    const int b   = row / HH;
    const int u   = threadIdx.x;         // 0..479
    const int w0  = u * 4;

    // ---- per-pixel warp indices/weights (channel-invariant) ----
    float4 dep = *reinterpret_cast<const float4*>(depth + (size_t)row * WW + w0);
    float d[4] = {dep.x, dep.y, dep.z, dep.w};

    int   i0L[4], i0R[4];
    float fL[4], fR[4];
#pragma unroll
    for (int p = 0; p < 4; ++p) {
        float disp = fminf(fmaxf(d[p] * MAXD, 0.0f), MAXD);
        float xw = (float)(w0 + p);

        float xl = fminf(fmaxf(xw - disp, 0.0f), (float)(WW - 1));
        int i0 = (int)xl;                    // xl >= 0 -> trunc == floor
        fL[p]  = xl - (float)i0;
        i0L[p] = i0;

        float xr = fminf(fmaxf(xw + disp, 0.0f), (float)(WW - 1));
        int j0 = (int)xr;
        fR[p]  = xr - (float)j0;
        i0R[p] = j0;
    }

    const int HW = HH * WW;
    const int N  = BATCH * CH * HW;          // 47,185,920 (fits int32)
    const int plane0 = b * (CH - 1) * HW + row * WW;   // == b*CH*HW + h*WW

#pragma unroll
    for (int c = 0; c < CH; ++c) {
        const int base = plane0 + c * HW;

        if (c) __syncthreads();              // protect smem before overwrite

        // stage rows: one float4 per thread per image (coalesced)
        float4 lv = *reinterpret_cast<const float4*>(img_l + base + w0);
        float4 rv = *reinterpret_cast<const float4*>(img_r + base + w0);
        *reinterpret_cast<float4*>(sl + w0) = lv;
        *reinterpret_cast<float4*>(sr + w0) = rv;
        __syncthreads();

        float lvv[4] = {lv.x, lv.y, lv.z, lv.w};
        float rvv[4] = {rv.x, rv.y, rv.z, rv.w};

        float ol[4], og[4];
#pragma unroll
        for (int p = 0; p < 4; ++p) {
            int a0 = i0L[p];
            int a1 = min(a0 + 1, WW - 1);
            int b0 = i0R[p];
            int b1 = min(b0 + 1, WW - 1);
            float wr = sr[a0] * (1.0f - fL[p]) + sr[a1] * fL[p];
            float wl = sl[b0] * (1.0f - fR[p]) + sl[b1] * fR[p];
            ol[p] = (lvv[p] + wr) * 0.5f;
            og[p] = (rvv[p] + wl) * 0.5f;
        }

        *reinterpret_cast<float4*>(out + base + w0) =
            make_float4(ol[0], ol[1], ol[2], ol[3]);
        *reinterpret_cast<float4*>(out + N + base + w0) =
            make_float4(og[0], og[1], og[2], og[3]);
    }
}

extern "C" void kernel_launch(void* const* d_in, const int* in_sizes, int n_in,
                              void* d_out, int out_size) {
    const float* img_l = (const float*)d_in[0];
    const float* img_r = (const float*)d_in[1];
    const float* depth = (const float*)d_in[2];
    float* out = (float*)d_out;

    const int blocks = BATCH * HH;           // one block per image row
    stereo_denoise_kernel<<<blocks, 480>>>(img_l, img_r, depth, out);
}